// round 10
// baseline (speedup 1.0000x reference)
#include <cuda_runtime.h>
#include <mma.h>
#include <cstdint>

using namespace nvcuda;

#define N_NODES 100000
#define E_EDGES 1600000
#define D_IN   64
#define D_HID  64
#define D_OUT  40
#define BN_EPS 1e-5f
#define ELL_W  64

// ---------------- scratch ----------------
__device__ float4 g_yt[(size_t)N_NODES * 32];   // [y(64) | t(64)] per row
__device__ float4 g_h[(size_t)N_NODES * 16];    // pre-BN h
__device__ float4 g_hn[(size_t)N_NODES * 16];   // relu(bn(h))
__device__ float4 g_po[(size_t)N_NODES * 20];   // [p(40) | oz(40)] per row
__device__ int    g_adj[(size_t)N_NODES * ELL_W];
__device__ int    g_cnt[N_NODES];
__device__ float  g_sum[D_HID];
__device__ float  g_sumsq[D_HID];

__device__ float4 g_W1[2048];      // stacked [W1l;W1r], 128 rows x 64 cols
__device__ float4 g_W2[1280];      // stacked [W2l;W2r], 80 rows x 64 cols
__device__ float  g_W1hi[8192], g_W1lo[8192];
__device__ float  g_W2hi[5120], g_W2lo[5120];
__constant__ float c_b1[D_HID];
__constant__ float c_b2[D_OUT];

// ---------------- init ----------------
__global__ void k_zero() {
    int i = blockIdx.x * blockDim.x + threadIdx.x;
    int stride = gridDim.x * blockDim.x;
    for (int t = i; t < N_NODES; t += stride) g_cnt[t] = 0;
    if (i < D_HID) { g_sum[i] = 0.f; g_sumsq[i] = 0.f; }
}

// ---- split weights into tf32 hi/lo (3xTF32 compensation) ----
__global__ void k_prep() {
    int i = blockIdx.x * blockDim.x + threadIdx.x;
    if (i < 8192) {
        float w = reinterpret_cast<const float*>(g_W1)[i];
        float hi = wmma::__float_to_tf32(w);
        g_W1hi[i] = hi;
        g_W1lo[i] = wmma::__float_to_tf32(w - hi);
    }
    if (i < 5120) {
        float w = reinterpret_cast<const float*>(g_W2)[i];
        float hi = wmma::__float_to_tf32(w);
        g_W2hi[i] = hi;
        g_W2lo[i] = wmma::__float_to_tf32(w - hi);
    }
}

// ---------------- single-pass ELL build ----------------
__global__ void k_countfill(const int* __restrict__ src, const int* __restrict__ dst) {
    int t = blockIdx.x * blockDim.x + threadIdx.x;
    int e = t * 8;
    if (e + 8 <= E_EDGES) {
        int4 da = *reinterpret_cast<const int4*>(dst + e);
        int4 db = *reinterpret_cast<const int4*>(dst + e + 4);
        int4 sa = *reinterpret_cast<const int4*>(src + e);
        int4 sb = *reinterpret_cast<const int4*>(src + e + 4);
        int p0 = atomicAdd(&g_cnt[da.x], 1);
        int p1 = atomicAdd(&g_cnt[da.y], 1);
        int p2 = atomicAdd(&g_cnt[da.z], 1);
        int p3 = atomicAdd(&g_cnt[da.w], 1);
        int p4 = atomicAdd(&g_cnt[db.x], 1);
        int p5 = atomicAdd(&g_cnt[db.y], 1);
        int p6 = atomicAdd(&g_cnt[db.z], 1);
        int p7 = atomicAdd(&g_cnt[db.w], 1);
        if (p0 < ELL_W) g_adj[(size_t)da.x * ELL_W + p0] = sa.x;
        if (p1 < ELL_W) g_adj[(size_t)da.y * ELL_W + p1] = sa.y;
        if (p2 < ELL_W) g_adj[(size_t)da.z * ELL_W + p2] = sa.z;
        if (p3 < ELL_W) g_adj[(size_t)da.w * ELL_W + p3] = sa.w;
        if (p4 < ELL_W) g_adj[(size_t)db.x * ELL_W + p4] = sb.x;
        if (p5 < ELL_W) g_adj[(size_t)db.y * ELL_W + p5] = sb.y;
        if (p6 < ELL_W) g_adj[(size_t)db.z * ELL_W + p6] = sb.z;
        if (p7 < ELL_W) g_adj[(size_t)db.w * ELL_W + p7] = sb.w;
    } else {
        for (int k = e; k < E_EDGES; k++) {
            int d = dst[k];
            int pos = atomicAdd(&g_cnt[d], 1);
            if (pos < ELL_W) g_adj[(size_t)d * ELL_W + pos] = src[k];
        }
    }
}

// ------- layer-1 projection (wmma tf32, 3x split): g_yt = x @ [W1l;W1r].T ----
// Warp = 16 rows; 8 n-tiles of 16 cols; K=64 in 8 steps.
__global__ __launch_bounds__(256) void k_proj1_w(const float* __restrict__ x) {
    int warp = (blockIdx.x * blockDim.x + threadIdx.x) >> 5;
    int m0 = warp * 16;
    if (m0 >= N_NODES) return;
    wmma::fragment<wmma::accumulator, 16, 16, 8, float> acc[8];
#pragma unroll
    for (int n = 0; n < 8; n++) wmma::fill_fragment(acc[n], 0.0f);
    wmma::fragment<wmma::matrix_a, 16, 16, 8, wmma::precision::tf32, wmma::row_major> a_raw, a_hi, a_lo;
    wmma::fragment<wmma::matrix_b, 16, 16, 8, wmma::precision::tf32, wmma::col_major> b_hi, b_lo;
#pragma unroll 1
    for (int k = 0; k < 8; k++) {
        wmma::load_matrix_sync(a_raw, x + (size_t)m0 * 64 + k * 8, 64);
#pragma unroll
        for (int i = 0; i < a_raw.num_elements; i++) {
            float hi = wmma::__float_to_tf32(a_raw.x[i]);
            a_hi.x[i] = hi;
            a_lo.x[i] = wmma::__float_to_tf32(a_raw.x[i] - hi);
        }
#pragma unroll
        for (int n = 0; n < 8; n++) {
            wmma::load_matrix_sync(b_hi, g_W1hi + n * 16 * 64 + k * 8, 64);
            wmma::load_matrix_sync(b_lo, g_W1lo + n * 16 * 64 + k * 8, 64);
            wmma::mma_sync(acc[n], a_hi, b_hi, acc[n]);
            wmma::mma_sync(acc[n], a_hi, b_lo, acc[n]);
            wmma::mma_sync(acc[n], a_lo, b_hi, acc[n]);
        }
    }
    float* yt = reinterpret_cast<float*>(g_yt);
#pragma unroll
    for (int n = 0; n < 8; n++)
        wmma::store_matrix_sync(yt + (size_t)m0 * 128 + n * 16, acc[n], 128, wmma::mem_row_major);
}

// ---- h = t + b1 + mean(y_neigh); fused BN column stats ----
__global__ __launch_bounds__(256) void k_agg1h() {
    int warp = threadIdx.x >> 5;
    int lane = threadIdx.x & 31;
    int sub = lane >> 4;
    int q = lane & 15;
    float4 sacc = make_float4(0.f, 0.f, 0.f, 0.f);
    float4 qacc = make_float4(0.f, 0.f, 0.f, 0.f);
    int n0 = blockIdx.x * 64;
#pragma unroll 1
    for (int it = 0; it < 4; it++) {
        int n = n0 + it * 16 + warp * 2 + sub;
        if (n >= N_NODES) continue;
        const int* row = g_adj + (size_t)n * ELL_W;
        int cnt = g_cnt[n];
        if (cnt > ELL_W) cnt = ELL_W;
        float4 acc = make_float4(0.f, 0.f, 0.f, 0.f);
        int i = 0;
        for (; i + 8 <= cnt; i += 8) {
            int4 s4 = *reinterpret_cast<const int4*>(row + i);
            int4 s8 = *reinterpret_cast<const int4*>(row + i + 4);
            float4 v0 = g_yt[(size_t)s4.x * 32 + q];
            float4 v1 = g_yt[(size_t)s4.y * 32 + q];
            float4 v2 = g_yt[(size_t)s4.z * 32 + q];
            float4 v3 = g_yt[(size_t)s4.w * 32 + q];
            float4 v4 = g_yt[(size_t)s8.x * 32 + q];
            float4 v5 = g_yt[(size_t)s8.y * 32 + q];
            float4 v6 = g_yt[(size_t)s8.z * 32 + q];
            float4 v7 = g_yt[(size_t)s8.w * 32 + q];
            acc.x += ((v0.x + v1.x) + (v2.x + v3.x)) + ((v4.x + v5.x) + (v6.x + v7.x));
            acc.y += ((v0.y + v1.y) + (v2.y + v3.y)) + ((v4.y + v5.y) + (v6.y + v7.y));
            acc.z += ((v0.z + v1.z) + (v2.z + v3.z)) + ((v4.z + v5.z) + (v6.z + v7.z));
            acc.w += ((v0.w + v1.w) + (v2.w + v3.w)) + ((v4.w + v5.w) + (v6.w + v7.w));
        }
        for (; i + 4 <= cnt; i += 4) {
            int4 s4 = *reinterpret_cast<const int4*>(row + i);
            float4 v0 = g_yt[(size_t)s4.x * 32 + q];
            float4 v1 = g_yt[(size_t)s4.y * 32 + q];
            float4 v2 = g_yt[(size_t)s4.z * 32 + q];
            float4 v3 = g_yt[(size_t)s4.w * 32 + q];
            acc.x += (v0.x + v1.x) + (v2.x + v3.x);
            acc.y += (v0.y + v1.y) + (v2.y + v3.y);
            acc.z += (v0.z + v1.z) + (v2.z + v3.z);
            acc.w += (v0.w + v1.w) + (v2.w + v3.w);
        }
        for (; i < cnt; i++) {
            int s = row[i];
            float4 v = g_yt[(size_t)s * 32 + q];
            acc.x += v.x; acc.y += v.y; acc.z += v.z; acc.w += v.w;
        }
        float inv = 1.0f / (float)(cnt > 0 ? cnt : 1);
        float4 t = g_yt[(size_t)n * 32 + 16 + q];
        float4 b = reinterpret_cast<const float4*>(c_b1)[q];
        float4 h;
        h.x = fmaf(acc.x, inv, t.x + b.x);
        h.y = fmaf(acc.y, inv, t.y + b.y);
        h.z = fmaf(acc.z, inv, t.z + b.z);
        h.w = fmaf(acc.w, inv, t.w + b.w);
        g_h[(size_t)n * 16 + q] = h;
        sacc.x += h.x; sacc.y += h.y; sacc.z += h.z; sacc.w += h.w;
        qacc.x += h.x * h.x; qacc.y += h.y * h.y; qacc.z += h.z * h.z; qacc.w += h.w * h.w;
    }
    __shared__ float4 ssum[256];
    __shared__ float4 ssq[256];
    ssum[threadIdx.x] = sacc;
    ssq[threadIdx.x] = qacc;
    __syncthreads();
    for (int stride = 128; stride >= 16; stride >>= 1) {
        if (threadIdx.x < stride) {
            float4 a = ssum[threadIdx.x + stride];
            float4 b = ssq[threadIdx.x + stride];
            float4 sa = ssum[threadIdx.x];
            float4 sb = ssq[threadIdx.x];
            sa.x += a.x; sa.y += a.y; sa.z += a.z; sa.w += a.w;
            sb.x += b.x; sb.y += b.y; sb.z += b.z; sb.w += b.w;
            ssum[threadIdx.x] = sa;
            ssq[threadIdx.x] = sb;
        }
        __syncthreads();
    }
    if (threadIdx.x < 16) {
        float4 sa = ssum[threadIdx.x];
        float4 sb = ssq[threadIdx.x];
        int jb = threadIdx.x * 4;
        atomicAdd(&g_sum[jb + 0], sa.x);
        atomicAdd(&g_sum[jb + 1], sa.y);
        atomicAdd(&g_sum[jb + 2], sa.z);
        atomicAdd(&g_sum[jb + 3], sa.w);
        atomicAdd(&g_sumsq[jb + 0], sb.x);
        atomicAdd(&g_sumsq[jb + 1], sb.y);
        atomicAdd(&g_sumsq[jb + 2], sb.z);
        atomicAdd(&g_sumsq[jb + 3], sb.w);
    }
}

// ---- materialize hn = relu(bn(h)) ----
__global__ __launch_bounds__(256) void k_bnrelu(const float* __restrict__ gamma,
                                                const float* __restrict__ beta) {
    __shared__ float4 s_scale[16];
    __shared__ float4 s_shift[16];
    if (threadIdx.x < D_HID) {
        int j = threadIdx.x;
        float mu = g_sum[j] * (1.0f / (float)N_NODES);
        float var = g_sumsq[j] * (1.0f / (float)N_NODES) - mu * mu;
        float rs = rsqrtf(var + BN_EPS);
        float sc = gamma[j] * rs;
        reinterpret_cast<float*>(s_scale)[j] = sc;
        reinterpret_cast<float*>(s_shift)[j] = beta[j] - mu * sc;
    }
    __syncthreads();
    int n = blockIdx.x * 256 + threadIdx.x;
    if (n >= N_NODES) return;
    const float4* hp = g_h + (size_t)n * 16;
    float4* op = g_hn + (size_t)n * 16;
#pragma unroll
    for (int c = 0; c < 16; c++) {
        float4 sc = s_scale[c];
        float4 sh = s_shift[c];
        float4 h = hp[c];
        h.x = fmaxf(fmaf(h.x, sc.x, sh.x), 0.f);
        h.y = fmaxf(fmaf(h.y, sc.y, sh.y), 0.f);
        h.z = fmaxf(fmaf(h.z, sc.z, sh.z), 0.f);
        h.w = fmaxf(fmaf(h.w, sc.w, sh.w), 0.f);
        op[c] = h;
    }
}

// ------- layer-2 projection (wmma tf32, 3x split): g_po = hn @ [W2l;W2r].T ----
__global__ __launch_bounds__(256) void k_proj2_w() {
    int warp = (blockIdx.x * blockDim.x + threadIdx.x) >> 5;
    int m0 = warp * 16;
    if (m0 >= N_NODES) return;
    const float* hn = reinterpret_cast<const float*>(g_hn);
    wmma::fragment<wmma::accumulator, 16, 16, 8, float> acc[5];
#pragma unroll
    for (int n = 0; n < 5; n++) wmma::fill_fragment(acc[n], 0.0f);
    wmma::fragment<wmma::matrix_a, 16, 16, 8, wmma::precision::tf32, wmma::row_major> a_raw, a_hi, a_lo;
    wmma::fragment<wmma::matrix_b, 16, 16, 8, wmma::precision::tf32, wmma::col_major> b_hi, b_lo;
#pragma unroll 1
    for (int k = 0; k < 8; k++) {
        wmma::load_matrix_sync(a_raw, hn + (size_t)m0 * 64 + k * 8, 64);
#pragma unroll
        for (int i = 0; i < a_raw.num_elements; i++) {
            float hi = wmma::__float_to_tf32(a_raw.x[i]);
            a_hi.x[i] = hi;
            a_lo.x[i] = wmma::__float_to_tf32(a_raw.x[i] - hi);
        }
#pragma unroll
        for (int n = 0; n < 5; n++) {
            wmma::load_matrix_sync(b_hi, g_W2hi + n * 16 * 64 + k * 8, 64);
            wmma::load_matrix_sync(b_lo, g_W2lo + n * 16 * 64 + k * 8, 64);
            wmma::mma_sync(acc[n], a_hi, b_hi, acc[n]);
            wmma::mma_sync(acc[n], a_hi, b_lo, acc[n]);
            wmma::mma_sync(acc[n], a_lo, b_hi, acc[n]);
        }
    }
    float* po = reinterpret_cast<float*>(g_po);
#pragma unroll
    for (int n = 0; n < 5; n++)
        wmma::store_matrix_sync(po + (size_t)m0 * 80 + n * 16, acc[n], 80, wmma::mem_row_major);
}

// ------- out[n] = oz + b2 + mean(p_neigh) -------
__global__ __launch_bounds__(256) void k_agg2(float4* __restrict__ out) {
    int gw = (blockIdx.x * blockDim.x + threadIdx.x) >> 5;
    int lane = threadIdx.x & 31;
    int sub = lane / 10;
    int q = lane - sub * 10;
    int n = gw * 3 + sub;
    if (sub >= 3 || n >= N_NODES) return;
    const int* row = g_adj + (size_t)n * ELL_W;
    int cnt = g_cnt[n];
    if (cnt > ELL_W) cnt = ELL_W;
    float4 acc = make_float4(0.f, 0.f, 0.f, 0.f);
    int i = 0;
    for (; i + 4 <= cnt; i += 4) {
        int4 s4 = *reinterpret_cast<const int4*>(row + i);
        float4 v0 = g_po[(size_t)s4.x * 20 + q];
        float4 v1 = g_po[(size_t)s4.y * 20 + q];
        float4 v2 = g_po[(size_t)s4.z * 20 + q];
        float4 v3 = g_po[(size_t)s4.w * 20 + q];
        acc.x += (v0.x + v1.x) + (v2.x + v3.x);
        acc.y += (v0.y + v1.y) + (v2.y + v3.y);
        acc.z += (v0.z + v1.z) + (v2.z + v3.z);
        acc.w += (v0.w + v1.w) + (v2.w + v3.w);
    }
    for (; i < cnt; i++) {
        int s = row[i];
        float4 v = g_po[(size_t)s * 20 + q];
        acc.x += v.x; acc.y += v.y; acc.z += v.z; acc.w += v.w;
    }
    float inv = 1.0f / (float)(cnt > 0 ? cnt : 1);
    float4 oz = g_po[(size_t)n * 20 + 10 + q];
    float4 b = reinterpret_cast<const float4*>(c_b2)[q];
    float4 o;
    o.x = fmaf(acc.x, inv, oz.x + b.x);
    o.y = fmaf(acc.y, inv, oz.y + b.y);
    o.z = fmaf(acc.z, inv, oz.z + b.z);
    o.w = fmaf(acc.w, inv, oz.w + b.w);
    out[(size_t)n * 10 + q] = o;
}

// ---------------- launch ----------------
extern "C" void kernel_launch(void* const* d_in, const int* in_sizes, int n_in,
                              void* d_out, int out_size) {
    const float* x     = (const float*)d_in[0];
    const int*   ei    = (const int*)d_in[1];
    const float* gamma = (const float*)d_in[5];
    const float* beta  = (const float*)d_in[6];
    const int* src = ei;
    const int* dst = ei + E_EDGES;

    cudaMemcpyToSymbolAsync(g_W1, d_in[2], D_HID * D_IN * sizeof(float), 0,     cudaMemcpyDeviceToDevice, 0);
    cudaMemcpyToSymbolAsync(g_W1, d_in[3], D_HID * D_IN * sizeof(float), 16384, cudaMemcpyDeviceToDevice, 0);
    cudaMemcpyToSymbolAsync(c_b1, d_in[4], D_HID * sizeof(float), 0,            cudaMemcpyDeviceToDevice, 0);
    cudaMemcpyToSymbolAsync(g_W2, d_in[7], D_OUT * D_HID * sizeof(float), 0,     cudaMemcpyDeviceToDevice, 0);
    cudaMemcpyToSymbolAsync(g_W2, d_in[8], D_OUT * D_HID * sizeof(float), 10240, cudaMemcpyDeviceToDevice, 0);
    cudaMemcpyToSymbolAsync(c_b2, d_in[9], D_OUT * sizeof(float), 0,             cudaMemcpyDeviceToDevice, 0);

    k_zero<<<256, 256>>>();
    k_prep<<<32, 256>>>();
    k_countfill<<<(E_EDGES / 8 + 255) / 256, 256>>>(src, dst);

    // Layer 1: tensor-core projection, then gather (+b1, fused BN stats)
    k_proj1_w<<<(N_NODES / 16 + 7) / 8, 256>>>(x);       // 6250 warp tiles
    k_agg1h<<<(N_NODES + 63) / 64, 256>>>();

    // BN finalize + ReLU materialize, layer-2 tensor-core projection
    k_bnrelu<<<(N_NODES + 255) / 256, 256>>>(gamma, beta);
    k_proj2_w<<<(N_NODES / 16 + 7) / 8, 256>>>();

    // Layer 2 gather: out = oz + b2 + mean(p)
    k_agg2<<<(N_NODES / 3 + 8) / 8, 256>>>((float4*)d_out);
}

// round 11
// speedup vs baseline: 1.2281x; 1.2281x over previous
#include <cuda_runtime.h>
#include <mma.h>
#include <cstdint>

using namespace nvcuda;

#define N_NODES 100000
#define E_EDGES 1600000
#define D_IN   64
#define D_HID  64
#define D_OUT  40
#define BN_EPS 1e-5f
#define ELL_W  64
#define LDB    68   // padded smem leading dim (floats): 68%32=4 -> <=4-way conflicts

// ---------------- scratch ----------------
__device__ float4 g_yt[(size_t)N_NODES * 32];   // [y(64) | t(64)] per row
__device__ float4 g_h[(size_t)N_NODES * 16];    // pre-BN h
__device__ float4 g_hn[(size_t)N_NODES * 16];   // relu(bn(h))
__device__ float4 g_po[(size_t)N_NODES * 20];   // [p(40) | oz(40)] per row
__device__ int    g_adj[(size_t)N_NODES * ELL_W];
__device__ int    g_cnt[N_NODES];
__device__ float  g_sum[D_HID];
__device__ float  g_sumsq[D_HID];

__device__ float4 g_W1[2048];      // stacked [W1l;W1r], 128 rows x 64 cols
__device__ float4 g_W2[1280];      // stacked [W2l;W2r], 80 rows x 64 cols
__constant__ float c_b1[D_HID];
__constant__ float c_b2[D_OUT];

// ---------------- init ----------------
__global__ void k_zero() {
    int i = blockIdx.x * blockDim.x + threadIdx.x;
    int stride = gridDim.x * blockDim.x;
    for (int t = i; t < N_NODES; t += stride) g_cnt[t] = 0;
    if (i < D_HID) { g_sum[i] = 0.f; g_sumsq[i] = 0.f; }
}

// ---------------- single-pass ELL build ----------------
__global__ void k_countfill(const int* __restrict__ src, const int* __restrict__ dst) {
    int t = blockIdx.x * blockDim.x + threadIdx.x;
    int e = t * 8;
    if (e + 8 <= E_EDGES) {
        int4 da = *reinterpret_cast<const int4*>(dst + e);
        int4 db = *reinterpret_cast<const int4*>(dst + e + 4);
        int4 sa = *reinterpret_cast<const int4*>(src + e);
        int4 sb = *reinterpret_cast<const int4*>(src + e + 4);
        int p0 = atomicAdd(&g_cnt[da.x], 1);
        int p1 = atomicAdd(&g_cnt[da.y], 1);
        int p2 = atomicAdd(&g_cnt[da.z], 1);
        int p3 = atomicAdd(&g_cnt[da.w], 1);
        int p4 = atomicAdd(&g_cnt[db.x], 1);
        int p5 = atomicAdd(&g_cnt[db.y], 1);
        int p6 = atomicAdd(&g_cnt[db.z], 1);
        int p7 = atomicAdd(&g_cnt[db.w], 1);
        if (p0 < ELL_W) g_adj[(size_t)da.x * ELL_W + p0] = sa.x;
        if (p1 < ELL_W) g_adj[(size_t)da.y * ELL_W + p1] = sa.y;
        if (p2 < ELL_W) g_adj[(size_t)da.z * ELL_W + p2] = sa.z;
        if (p3 < ELL_W) g_adj[(size_t)da.w * ELL_W + p3] = sa.w;
        if (p4 < ELL_W) g_adj[(size_t)db.x * ELL_W + p4] = sb.x;
        if (p5 < ELL_W) g_adj[(size_t)db.y * ELL_W + p5] = sb.y;
        if (p6 < ELL_W) g_adj[(size_t)db.z * ELL_W + p6] = sb.z;
        if (p7 < ELL_W) g_adj[(size_t)db.w * ELL_W + p7] = sb.w;
    } else {
        for (int k = e; k < E_EDGES; k++) {
            int d = dst[k];
            int pos = atomicAdd(&g_cnt[d], 1);
            if (pos < ELL_W) g_adj[(size_t)d * ELL_W + pos] = src[k];
        }
    }
}

// ------- layer-1 projection (wmma tf32 3x, smem-staged B): g_yt = x @ W1s.T --
// Block = 8 warps = 128 rows. Dynamic smem: B hi then B lo, each 128 x LDB.
__global__ __launch_bounds__(256) void k_proj1_w(const float* __restrict__ x) {
    extern __shared__ float sB[];
    float* sBhi = sB;
    float* sBlo = sB + 128 * LDB;
    const float* W = reinterpret_cast<const float*>(g_W1);
    for (int i = threadIdx.x; i < 8192; i += 256) {
        int r = i >> 6, c = i & 63;
        float w = W[i];
        float hi = wmma::__float_to_tf32(w);
        sBhi[r * LDB + c] = hi;
        sBlo[r * LDB + c] = wmma::__float_to_tf32(w - hi);
    }
    __syncthreads();
    int m0 = blockIdx.x * 128 + (threadIdx.x >> 5) * 16;
    if (m0 >= N_NODES) return;
    wmma::fragment<wmma::accumulator, 16, 16, 8, float> acc[8];
#pragma unroll
    for (int n = 0; n < 8; n++) wmma::fill_fragment(acc[n], 0.0f);
    wmma::fragment<wmma::matrix_a, 16, 16, 8, wmma::precision::tf32, wmma::row_major> a_raw, a_hi, a_lo;
    wmma::fragment<wmma::matrix_b, 16, 16, 8, wmma::precision::tf32, wmma::col_major> b_hi, b_lo;
#pragma unroll 1
    for (int k = 0; k < 8; k++) {
        wmma::load_matrix_sync(a_raw, x + (size_t)m0 * 64 + k * 8, 64);
#pragma unroll
        for (int i = 0; i < a_raw.num_elements; i++) {
            float hi = wmma::__float_to_tf32(a_raw.x[i]);
            a_hi.x[i] = hi;
            a_lo.x[i] = wmma::__float_to_tf32(a_raw.x[i] - hi);
        }
#pragma unroll
        for (int n = 0; n < 8; n++) {
            wmma::load_matrix_sync(b_hi, sBhi + n * 16 * LDB + k * 8, LDB);
            wmma::load_matrix_sync(b_lo, sBlo + n * 16 * LDB + k * 8, LDB);
            wmma::mma_sync(acc[n], a_hi, b_hi, acc[n]);
            wmma::mma_sync(acc[n], a_hi, b_lo, acc[n]);
            wmma::mma_sync(acc[n], a_lo, b_hi, acc[n]);
        }
    }
    float* yt = reinterpret_cast<float*>(g_yt);
#pragma unroll
    for (int n = 0; n < 8; n++)
        wmma::store_matrix_sync(yt + (size_t)m0 * 128 + n * 16, acc[n], 128, wmma::mem_row_major);
}

// ---- h = t + b1 + mean(y_neigh); fused BN column stats ----
__global__ __launch_bounds__(256) void k_agg1h() {
    int warp = threadIdx.x >> 5;
    int lane = threadIdx.x & 31;
    int sub = lane >> 4;
    int q = lane & 15;
    float4 sacc = make_float4(0.f, 0.f, 0.f, 0.f);
    float4 qacc = make_float4(0.f, 0.f, 0.f, 0.f);
    int n0 = blockIdx.x * 64;
#pragma unroll 1
    for (int it = 0; it < 4; it++) {
        int n = n0 + it * 16 + warp * 2 + sub;
        if (n >= N_NODES) continue;
        const int* row = g_adj + (size_t)n * ELL_W;
        int cnt = g_cnt[n];
        if (cnt > ELL_W) cnt = ELL_W;
        float4 acc = make_float4(0.f, 0.f, 0.f, 0.f);
        int i = 0;
        for (; i + 8 <= cnt; i += 8) {
            int4 s4 = *reinterpret_cast<const int4*>(row + i);
            int4 s8 = *reinterpret_cast<const int4*>(row + i + 4);
            float4 v0 = g_yt[(size_t)s4.x * 32 + q];
            float4 v1 = g_yt[(size_t)s4.y * 32 + q];
            float4 v2 = g_yt[(size_t)s4.z * 32 + q];
            float4 v3 = g_yt[(size_t)s4.w * 32 + q];
            float4 v4 = g_yt[(size_t)s8.x * 32 + q];
            float4 v5 = g_yt[(size_t)s8.y * 32 + q];
            float4 v6 = g_yt[(size_t)s8.z * 32 + q];
            float4 v7 = g_yt[(size_t)s8.w * 32 + q];
            acc.x += ((v0.x + v1.x) + (v2.x + v3.x)) + ((v4.x + v5.x) + (v6.x + v7.x));
            acc.y += ((v0.y + v1.y) + (v2.y + v3.y)) + ((v4.y + v5.y) + (v6.y + v7.y));
            acc.z += ((v0.z + v1.z) + (v2.z + v3.z)) + ((v4.z + v5.z) + (v6.z + v7.z));
            acc.w += ((v0.w + v1.w) + (v2.w + v3.w)) + ((v4.w + v5.w) + (v6.w + v7.w));
        }
        for (; i + 4 <= cnt; i += 4) {
            int4 s4 = *reinterpret_cast<const int4*>(row + i);
            float4 v0 = g_yt[(size_t)s4.x * 32 + q];
            float4 v1 = g_yt[(size_t)s4.y * 32 + q];
            float4 v2 = g_yt[(size_t)s4.z * 32 + q];
            float4 v3 = g_yt[(size_t)s4.w * 32 + q];
            acc.x += (v0.x + v1.x) + (v2.x + v3.x);
            acc.y += (v0.y + v1.y) + (v2.y + v3.y);
            acc.z += (v0.z + v1.z) + (v2.z + v3.z);
            acc.w += (v0.w + v1.w) + (v2.w + v3.w);
        }
        for (; i < cnt; i++) {
            int s = row[i];
            float4 v = g_yt[(size_t)s * 32 + q];
            acc.x += v.x; acc.y += v.y; acc.z += v.z; acc.w += v.w;
        }
        float inv = 1.0f / (float)(cnt > 0 ? cnt : 1);
        float4 t = g_yt[(size_t)n * 32 + 16 + q];
        float4 b = reinterpret_cast<const float4*>(c_b1)[q];
        float4 h;
        h.x = fmaf(acc.x, inv, t.x + b.x);
        h.y = fmaf(acc.y, inv, t.y + b.y);
        h.z = fmaf(acc.z, inv, t.z + b.z);
        h.w = fmaf(acc.w, inv, t.w + b.w);
        g_h[(size_t)n * 16 + q] = h;
        sacc.x += h.x; sacc.y += h.y; sacc.z += h.z; sacc.w += h.w;
        qacc.x += h.x * h.x; qacc.y += h.y * h.y; qacc.z += h.z * h.z; qacc.w += h.w * h.w;
    }
    __shared__ float4 ssum[256];
    __shared__ float4 ssq[256];
    ssum[threadIdx.x] = sacc;
    ssq[threadIdx.x] = qacc;
    __syncthreads();
    for (int stride = 128; stride >= 16; stride >>= 1) {
        if (threadIdx.x < stride) {
            float4 a = ssum[threadIdx.x + stride];
            float4 b = ssq[threadIdx.x + stride];
            float4 sa = ssum[threadIdx.x];
            float4 sb = ssq[threadIdx.x];
            sa.x += a.x; sa.y += a.y; sa.z += a.z; sa.w += a.w;
            sb.x += b.x; sb.y += b.y; sb.z += b.z; sb.w += b.w;
            ssum[threadIdx.x] = sa;
            ssq[threadIdx.x] = sb;
        }
        __syncthreads();
    }
    if (threadIdx.x < 16) {
        float4 sa = ssum[threadIdx.x];
        float4 sb = ssq[threadIdx.x];
        int jb = threadIdx.x * 4;
        atomicAdd(&g_sum[jb + 0], sa.x);
        atomicAdd(&g_sum[jb + 1], sa.y);
        atomicAdd(&g_sum[jb + 2], sa.z);
        atomicAdd(&g_sum[jb + 3], sa.w);
        atomicAdd(&g_sumsq[jb + 0], sb.x);
        atomicAdd(&g_sumsq[jb + 1], sb.y);
        atomicAdd(&g_sumsq[jb + 2], sb.z);
        atomicAdd(&g_sumsq[jb + 3], sb.w);
    }
}

// ---- materialize hn = relu(bn(h)) ----
__global__ __launch_bounds__(256) void k_bnrelu(const float* __restrict__ gamma,
                                                const float* __restrict__ beta) {
    __shared__ float4 s_scale[16];
    __shared__ float4 s_shift[16];
    if (threadIdx.x < D_HID) {
        int j = threadIdx.x;
        float mu = g_sum[j] * (1.0f / (float)N_NODES);
        float var = g_sumsq[j] * (1.0f / (float)N_NODES) - mu * mu;
        float rs = rsqrtf(var + BN_EPS);
        float sc = gamma[j] * rs;
        reinterpret_cast<float*>(s_scale)[j] = sc;
        reinterpret_cast<float*>(s_shift)[j] = beta[j] - mu * sc;
    }
    __syncthreads();
    int n = blockIdx.x * 256 + threadIdx.x;
    if (n >= N_NODES) return;
    const float4* hp = g_h + (size_t)n * 16;
    float4* op = g_hn + (size_t)n * 16;
#pragma unroll
    for (int c = 0; c < 16; c++) {
        float4 sc = s_scale[c];
        float4 sh = s_shift[c];
        float4 h = hp[c];
        h.x = fmaxf(fmaf(h.x, sc.x, sh.x), 0.f);
        h.y = fmaxf(fmaf(h.y, sc.y, sh.y), 0.f);
        h.z = fmaxf(fmaf(h.z, sc.z, sh.z), 0.f);
        h.w = fmaxf(fmaf(h.w, sc.w, sh.w), 0.f);
        op[c] = h;
    }
}

// ------- layer-2 projection (wmma tf32 3x, smem B): g_po = hn @ W2s.T -------
__global__ __launch_bounds__(256) void k_proj2_w() {
    __shared__ float sBhi[80 * LDB];
    __shared__ float sBlo[80 * LDB];
    const float* W = reinterpret_cast<const float*>(g_W2);
    for (int i = threadIdx.x; i < 5120; i += 256) {
        int r = i >> 6, c = i & 63;
        float w = W[i];
        float hi = wmma::__float_to_tf32(w);
        sBhi[r * LDB + c] = hi;
        sBlo[r * LDB + c] = wmma::__float_to_tf32(w - hi);
    }
    __syncthreads();
    int m0 = blockIdx.x * 128 + (threadIdx.x >> 5) * 16;
    if (m0 >= N_NODES) return;
    const float* hn = reinterpret_cast<const float*>(g_hn);
    wmma::fragment<wmma::accumulator, 16, 16, 8, float> acc[5];
#pragma unroll
    for (int n = 0; n < 5; n++) wmma::fill_fragment(acc[n], 0.0f);
    wmma::fragment<wmma::matrix_a, 16, 16, 8, wmma::precision::tf32, wmma::row_major> a_raw, a_hi, a_lo;
    wmma::fragment<wmma::matrix_b, 16, 16, 8, wmma::precision::tf32, wmma::col_major> b_hi, b_lo;
#pragma unroll 1
    for (int k = 0; k < 8; k++) {
        wmma::load_matrix_sync(a_raw, hn + (size_t)m0 * 64 + k * 8, 64);
#pragma unroll
        for (int i = 0; i < a_raw.num_elements; i++) {
            float hi = wmma::__float_to_tf32(a_raw.x[i]);
            a_hi.x[i] = hi;
            a_lo.x[i] = wmma::__float_to_tf32(a_raw.x[i] - hi);
        }
#pragma unroll
        for (int n = 0; n < 5; n++) {
            wmma::load_matrix_sync(b_hi, sBhi + n * 16 * LDB + k * 8, LDB);
            wmma::load_matrix_sync(b_lo, sBlo + n * 16 * LDB + k * 8, LDB);
            wmma::mma_sync(acc[n], a_hi, b_hi, acc[n]);
            wmma::mma_sync(acc[n], a_hi, b_lo, acc[n]);
            wmma::mma_sync(acc[n], a_lo, b_hi, acc[n]);
        }
    }
    float* po = reinterpret_cast<float*>(g_po);
#pragma unroll
    for (int n = 0; n < 5; n++)
        wmma::store_matrix_sync(po + (size_t)m0 * 80 + n * 16, acc[n], 80, wmma::mem_row_major);
}

// ------- out[n] = oz + b2 + mean(p_neigh) -------
__global__ __launch_bounds__(256) void k_agg2(float4* __restrict__ out) {
    int gw = (blockIdx.x * blockDim.x + threadIdx.x) >> 5;
    int lane = threadIdx.x & 31;
    int sub = lane / 10;
    int q = lane - sub * 10;
    int n = gw * 3 + sub;
    if (sub >= 3 || n >= N_NODES) return;
    const int* row = g_adj + (size_t)n * ELL_W;
    int cnt = g_cnt[n];
    if (cnt > ELL_W) cnt = ELL_W;
    float4 acc = make_float4(0.f, 0.f, 0.f, 0.f);
    int i = 0;
    for (; i + 4 <= cnt; i += 4) {
        int4 s4 = *reinterpret_cast<const int4*>(row + i);
        float4 v0 = g_po[(size_t)s4.x * 20 + q];
        float4 v1 = g_po[(size_t)s4.y * 20 + q];
        float4 v2 = g_po[(size_t)s4.z * 20 + q];
        float4 v3 = g_po[(size_t)s4.w * 20 + q];
        acc.x += (v0.x + v1.x) + (v2.x + v3.x);
        acc.y += (v0.y + v1.y) + (v2.y + v3.y);
        acc.z += (v0.z + v1.z) + (v2.z + v3.z);
        acc.w += (v0.w + v1.w) + (v2.w + v3.w);
    }
    for (; i < cnt; i++) {
        int s = row[i];
        float4 v = g_po[(size_t)s * 20 + q];
        acc.x += v.x; acc.y += v.y; acc.z += v.z; acc.w += v.w;
    }
    float inv = 1.0f / (float)(cnt > 0 ? cnt : 1);
    float4 oz = g_po[(size_t)n * 20 + 10 + q];
    float4 b = reinterpret_cast<const float4*>(c_b2)[q];
    float4 o;
    o.x = fmaf(acc.x, inv, oz.x + b.x);
    o.y = fmaf(acc.y, inv, oz.y + b.y);
    o.z = fmaf(acc.z, inv, oz.z + b.z);
    o.w = fmaf(acc.w, inv, oz.w + b.w);
    out[(size_t)n * 10 + q] = o;
}

// ---------------- launch ----------------
extern "C" void kernel_launch(void* const* d_in, const int* in_sizes, int n_in,
                              void* d_out, int out_size) {
    const float* x     = (const float*)d_in[0];
    const int*   ei    = (const int*)d_in[1];
    const float* gamma = (const float*)d_in[5];
    const float* beta  = (const float*)d_in[6];
    const int* src = ei;
    const int* dst = ei + E_EDGES;

    cudaMemcpyToSymbolAsync(g_W1, d_in[2], D_HID * D_IN * sizeof(float), 0,     cudaMemcpyDeviceToDevice, 0);
    cudaMemcpyToSymbolAsync(g_W1, d_in[3], D_HID * D_IN * sizeof(float), 16384, cudaMemcpyDeviceToDevice, 0);
    cudaMemcpyToSymbolAsync(c_b1, d_in[4], D_HID * sizeof(float), 0,            cudaMemcpyDeviceToDevice, 0);
    cudaMemcpyToSymbolAsync(g_W2, d_in[7], D_OUT * D_HID * sizeof(float), 0,     cudaMemcpyDeviceToDevice, 0);
    cudaMemcpyToSymbolAsync(g_W2, d_in[8], D_OUT * D_HID * sizeof(float), 10240, cudaMemcpyDeviceToDevice, 0);
    cudaMemcpyToSymbolAsync(c_b2, d_in[9], D_OUT * sizeof(float), 0,             cudaMemcpyDeviceToDevice, 0);

    const int p1_smem = 2 * 128 * LDB * (int)sizeof(float);   // 69632 B
    cudaFuncSetAttribute(k_proj1_w, cudaFuncAttributeMaxDynamicSharedMemorySize, p1_smem);

    k_zero<<<256, 256>>>();
    k_countfill<<<(E_EDGES / 8 + 255) / 256, 256>>>(src, dst);

    // Layer 1: tensor-core projection (smem B), then gather (+b1, BN stats)
    k_proj1_w<<<(N_NODES + 127) / 128, 256, p1_smem>>>(x);
    k_agg1h<<<(N_NODES + 63) / 64, 256>>>();

    // BN finalize + ReLU materialize, layer-2 tensor-core projection
    k_bnrelu<<<(N_NODES + 255) / 256, 256>>>(gamma, beta);
    k_proj2_w<<<(N_NODES + 127) / 128, 256>>>();

    // Layer 2 gather: out = oz + b2 + mean(p)
    k_agg2<<<(N_NODES / 3 + 8) / 8, 256>>>((float4*)d_out);
}

// round 12
// speedup vs baseline: 1.3046x; 1.0622x over previous
#include <cuda_runtime.h>
#include <mma.h>
#include <cstdint>

using namespace nvcuda;

#define N_NODES 100000
#define E_EDGES 1600000
#define D_IN   64
#define D_HID  64
#define D_OUT  40
#define BN_EPS 1e-5f
#define ELL_W  64
#define LDB    68   // padded smem leading dim (floats)

// ---------------- scratch ----------------
__device__ float4 g_yt[(size_t)N_NODES * 32];   // [y(64) | t(64)] per row
__device__ float4 g_h[(size_t)N_NODES * 16];    // pre-BN h
__device__ float4 g_po[(size_t)N_NODES * 20];   // [p(40) | oz(40)] per row
__device__ int    g_adj[(size_t)N_NODES * ELL_W];
__device__ int    g_cnt[N_NODES];
__device__ float  g_sum[D_HID];
__device__ float  g_sumsq[D_HID];

__device__ float4 g_W1[2048];      // stacked [W1l;W1r], 128 rows x 64 cols
__device__ float4 g_W2[1280];      // stacked [W2l;W2r], 80 rows x 64 cols
__constant__ float c_b1[D_HID];
__constant__ float c_b2[D_OUT];

// ---------------- init ----------------
__global__ void k_zero() {
    int i = blockIdx.x * blockDim.x + threadIdx.x;
    int stride = gridDim.x * blockDim.x;
    for (int t = i; t < N_NODES; t += stride) g_cnt[t] = 0;
    if (i < D_HID) { g_sum[i] = 0.f; g_sumsq[i] = 0.f; }
}

// ---------------- single-pass ELL build ----------------
__global__ void k_countfill(const int* __restrict__ src, const int* __restrict__ dst) {
    int t = blockIdx.x * blockDim.x + threadIdx.x;
    int e = t * 8;
    if (e + 8 <= E_EDGES) {
        int4 da = *reinterpret_cast<const int4*>(dst + e);
        int4 db = *reinterpret_cast<const int4*>(dst + e + 4);
        int4 sa = *reinterpret_cast<const int4*>(src + e);
        int4 sb = *reinterpret_cast<const int4*>(src + e + 4);
        int p0 = atomicAdd(&g_cnt[da.x], 1);
        int p1 = atomicAdd(&g_cnt[da.y], 1);
        int p2 = atomicAdd(&g_cnt[da.z], 1);
        int p3 = atomicAdd(&g_cnt[da.w], 1);
        int p4 = atomicAdd(&g_cnt[db.x], 1);
        int p5 = atomicAdd(&g_cnt[db.y], 1);
        int p6 = atomicAdd(&g_cnt[db.z], 1);
        int p7 = atomicAdd(&g_cnt[db.w], 1);
        if (p0 < ELL_W) g_adj[(size_t)da.x * ELL_W + p0] = sa.x;
        if (p1 < ELL_W) g_adj[(size_t)da.y * ELL_W + p1] = sa.y;
        if (p2 < ELL_W) g_adj[(size_t)da.z * ELL_W + p2] = sa.z;
        if (p3 < ELL_W) g_adj[(size_t)da.w * ELL_W + p3] = sa.w;
        if (p4 < ELL_W) g_adj[(size_t)db.x * ELL_W + p4] = sb.x;
        if (p5 < ELL_W) g_adj[(size_t)db.y * ELL_W + p5] = sb.y;
        if (p6 < ELL_W) g_adj[(size_t)db.z * ELL_W + p6] = sb.z;
        if (p7 < ELL_W) g_adj[(size_t)db.w * ELL_W + p7] = sb.w;
    } else {
        for (int k = e; k < E_EDGES; k++) {
            int d = dst[k];
            int pos = atomicAdd(&g_cnt[d], 1);
            if (pos < ELL_W) g_adj[(size_t)d * ELL_W + pos] = src[k];
        }
    }
}

// ------- layer-1 projection (wmma tf32 3x, smem-staged B): g_yt = x @ W1s.T --
__global__ __launch_bounds__(256) void k_proj1_w(const float* __restrict__ x) {
    extern __shared__ float sB[];
    float* sBhi = sB;
    float* sBlo = sB + 128 * LDB;
    const float* W = reinterpret_cast<const float*>(g_W1);
    for (int i = threadIdx.x; i < 8192; i += 256) {
        int r = i >> 6, c = i & 63;
        float w = W[i];
        float hi = wmma::__float_to_tf32(w);
        sBhi[r * LDB + c] = hi;
        sBlo[r * LDB + c] = wmma::__float_to_tf32(w - hi);
    }
    __syncthreads();
    int m0 = blockIdx.x * 128 + (threadIdx.x >> 5) * 16;
    if (m0 >= N_NODES) return;
    wmma::fragment<wmma::accumulator, 16, 16, 8, float> acc[8];
#pragma unroll
    for (int n = 0; n < 8; n++) wmma::fill_fragment(acc[n], 0.0f);
    wmma::fragment<wmma::matrix_a, 16, 16, 8, wmma::precision::tf32, wmma::row_major> a_raw, a_hi, a_lo;
    wmma::fragment<wmma::matrix_b, 16, 16, 8, wmma::precision::tf32, wmma::col_major> b_hi, b_lo;
#pragma unroll 1
    for (int k = 0; k < 8; k++) {
        wmma::load_matrix_sync(a_raw, x + (size_t)m0 * 64 + k * 8, 64);
#pragma unroll
        for (int i = 0; i < a_raw.num_elements; i++) {
            float hi = wmma::__float_to_tf32(a_raw.x[i]);
            a_hi.x[i] = hi;
            a_lo.x[i] = wmma::__float_to_tf32(a_raw.x[i] - hi);
        }
#pragma unroll
        for (int n = 0; n < 8; n++) {
            wmma::load_matrix_sync(b_hi, sBhi + n * 16 * LDB + k * 8, LDB);
            wmma::load_matrix_sync(b_lo, sBlo + n * 16 * LDB + k * 8, LDB);
            wmma::mma_sync(acc[n], a_hi, b_hi, acc[n]);
            wmma::mma_sync(acc[n], a_hi, b_lo, acc[n]);
            wmma::mma_sync(acc[n], a_lo, b_hi, acc[n]);
        }
    }
    float* yt = reinterpret_cast<float*>(g_yt);
#pragma unroll
    for (int n = 0; n < 8; n++)
        wmma::store_matrix_sync(yt + (size_t)m0 * 128 + n * 16, acc[n], 128, wmma::mem_row_major);
}

// ---- h = t + b1 + mean(y_neigh); fused BN column stats ----
__global__ __launch_bounds__(256) void k_agg1h() {
    int warp = threadIdx.x >> 5;
    int lane = threadIdx.x & 31;
    int sub = lane >> 4;
    int q = lane & 15;
    float4 sacc = make_float4(0.f, 0.f, 0.f, 0.f);
    float4 qacc = make_float4(0.f, 0.f, 0.f, 0.f);
    int n0 = blockIdx.x * 64;
#pragma unroll 1
    for (int it = 0; it < 4; it++) {
        int n = n0 + it * 16 + warp * 2 + sub;
        if (n >= N_NODES) continue;
        const int* row = g_adj + (size_t)n * ELL_W;
        int cnt = g_cnt[n];
        if (cnt > ELL_W) cnt = ELL_W;
        float4 acc = make_float4(0.f, 0.f, 0.f, 0.f);
        int i = 0;
        for (; i + 8 <= cnt; i += 8) {
            int4 s4 = *reinterpret_cast<const int4*>(row + i);
            int4 s8 = *reinterpret_cast<const int4*>(row + i + 4);
            float4 v0 = g_yt[(size_t)s4.x * 32 + q];
            float4 v1 = g_yt[(size_t)s4.y * 32 + q];
            float4 v2 = g_yt[(size_t)s4.z * 32 + q];
            float4 v3 = g_yt[(size_t)s4.w * 32 + q];
            float4 v4 = g_yt[(size_t)s8.x * 32 + q];
            float4 v5 = g_yt[(size_t)s8.y * 32 + q];
            float4 v6 = g_yt[(size_t)s8.z * 32 + q];
            float4 v7 = g_yt[(size_t)s8.w * 32 + q];
            acc.x += ((v0.x + v1.x) + (v2.x + v3.x)) + ((v4.x + v5.x) + (v6.x + v7.x));
            acc.y += ((v0.y + v1.y) + (v2.y + v3.y)) + ((v4.y + v5.y) + (v6.y + v7.y));
            acc.z += ((v0.z + v1.z) + (v2.z + v3.z)) + ((v4.z + v5.z) + (v6.z + v7.z));
            acc.w += ((v0.w + v1.w) + (v2.w + v3.w)) + ((v4.w + v5.w) + (v6.w + v7.w));
        }
        for (; i + 4 <= cnt; i += 4) {
            int4 s4 = *reinterpret_cast<const int4*>(row + i);
            float4 v0 = g_yt[(size_t)s4.x * 32 + q];
            float4 v1 = g_yt[(size_t)s4.y * 32 + q];
            float4 v2 = g_yt[(size_t)s4.z * 32 + q];
            float4 v3 = g_yt[(size_t)s4.w * 32 + q];
            acc.x += (v0.x + v1.x) + (v2.x + v3.x);
            acc.y += (v0.y + v1.y) + (v2.y + v3.y);
            acc.z += (v0.z + v1.z) + (v2.z + v3.z);
            acc.w += (v0.w + v1.w) + (v2.w + v3.w);
        }
        for (; i < cnt; i++) {
            int s = row[i];
            float4 v = g_yt[(size_t)s * 32 + q];
            acc.x += v.x; acc.y += v.y; acc.z += v.z; acc.w += v.w;
        }
        float inv = 1.0f / (float)(cnt > 0 ? cnt : 1);
        float4 t = g_yt[(size_t)n * 32 + 16 + q];
        float4 b = reinterpret_cast<const float4*>(c_b1)[q];
        float4 h;
        h.x = fmaf(acc.x, inv, t.x + b.x);
        h.y = fmaf(acc.y, inv, t.y + b.y);
        h.z = fmaf(acc.z, inv, t.z + b.z);
        h.w = fmaf(acc.w, inv, t.w + b.w);
        g_h[(size_t)n * 16 + q] = h;
        sacc.x += h.x; sacc.y += h.y; sacc.z += h.z; sacc.w += h.w;
        qacc.x += h.x * h.x; qacc.y += h.y * h.y; qacc.z += h.z * h.z; qacc.w += h.w * h.w;
    }
    __shared__ float4 ssum[256];
    __shared__ float4 ssq[256];
    ssum[threadIdx.x] = sacc;
    ssq[threadIdx.x] = qacc;
    __syncthreads();
    for (int stride = 128; stride >= 16; stride >>= 1) {
        if (threadIdx.x < stride) {
            float4 a = ssum[threadIdx.x + stride];
            float4 b = ssq[threadIdx.x + stride];
            float4 sa = ssum[threadIdx.x];
            float4 sb = ssq[threadIdx.x];
            sa.x += a.x; sa.y += a.y; sa.z += a.z; sa.w += a.w;
            sb.x += b.x; sb.y += b.y; sb.z += b.z; sb.w += b.w;
            ssum[threadIdx.x] = sa;
            ssq[threadIdx.x] = sb;
        }
        __syncthreads();
    }
    if (threadIdx.x < 16) {
        float4 sa = ssum[threadIdx.x];
        float4 sb = ssq[threadIdx.x];
        int jb = threadIdx.x * 4;
        atomicAdd(&g_sum[jb + 0], sa.x);
        atomicAdd(&g_sum[jb + 1], sa.y);
        atomicAdd(&g_sum[jb + 2], sa.z);
        atomicAdd(&g_sum[jb + 3], sa.w);
        atomicAdd(&g_sumsq[jb + 0], sb.x);
        atomicAdd(&g_sumsq[jb + 1], sb.y);
        atomicAdd(&g_sumsq[jb + 2], sb.z);
        atomicAdd(&g_sumsq[jb + 3], sb.w);
    }
}

// ---- BN finalize + ReLU (in smem staging) + layer-2 projection (wmma) ----
// Dynamic smem: sA[128*LDB] | sBhi[80*LDB] | sBlo[80*LDB]
__global__ __launch_bounds__(256) void k_bnproj2(const float* __restrict__ gamma,
                                                 const float* __restrict__ beta) {
    extern __shared__ float sm2[];
    float* sA = sm2;
    float* sBhi = sm2 + 128 * LDB;
    float* sBlo = sBhi + 80 * LDB;
    __shared__ float s_scale[D_HID];
    __shared__ float s_shift[D_HID];
    if (threadIdx.x < D_HID) {
        int j = threadIdx.x;
        float mu = g_sum[j] * (1.0f / (float)N_NODES);
        float var = g_sumsq[j] * (1.0f / (float)N_NODES) - mu * mu;
        float rs = rsqrtf(var + BN_EPS);
        float sc = gamma[j] * rs;
        s_scale[j] = sc;
        s_shift[j] = beta[j] - mu * sc;
    }
    // stage B (independent of scale/shift)
    const float* W = reinterpret_cast<const float*>(g_W2);
    for (int i = threadIdx.x; i < 5120; i += 256) {
        int r = i >> 6, c = i & 63;
        float w = W[i];
        float hi = wmma::__float_to_tf32(w);
        sBhi[r * LDB + c] = hi;
        sBlo[r * LDB + c] = wmma::__float_to_tf32(w - hi);
    }
    __syncthreads();
    // stage A = relu(bn(h)) for this block's 128 rows
    int base = blockIdx.x * 128;
    const float* hg = reinterpret_cast<const float*>(g_h);
    for (int i = threadIdx.x; i < 8192; i += 256) {
        int r = i >> 6, c = i & 63;
        int n = base + r;
        float v = 0.f;
        if (n < N_NODES)
            v = fmaxf(fmaf(hg[(size_t)n * 64 + c], s_scale[c], s_shift[c]), 0.f);
        sA[r * LDB + c] = v;
    }
    __syncthreads();
    int m0 = base + (threadIdx.x >> 5) * 16;
    if (m0 >= N_NODES) return;
    const float* sAw = sA + (threadIdx.x >> 5) * 16 * LDB;
    wmma::fragment<wmma::accumulator, 16, 16, 8, float> acc[5];
#pragma unroll
    for (int n = 0; n < 5; n++) wmma::fill_fragment(acc[n], 0.0f);
    wmma::fragment<wmma::matrix_a, 16, 16, 8, wmma::precision::tf32, wmma::row_major> a_raw, a_hi, a_lo;
    wmma::fragment<wmma::matrix_b, 16, 16, 8, wmma::precision::tf32, wmma::col_major> b_hi, b_lo;
#pragma unroll 1
    for (int k = 0; k < 8; k++) {
        wmma::load_matrix_sync(a_raw, sAw + k * 8, LDB);
#pragma unroll
        for (int i = 0; i < a_raw.num_elements; i++) {
            float hi = wmma::__float_to_tf32(a_raw.x[i]);
            a_hi.x[i] = hi;
            a_lo.x[i] = wmma::__float_to_tf32(a_raw.x[i] - hi);
        }
#pragma unroll
        for (int n = 0; n < 5; n++) {
            wmma::load_matrix_sync(b_hi, sBhi + n * 16 * LDB + k * 8, LDB);
            wmma::load_matrix_sync(b_lo, sBlo + n * 16 * LDB + k * 8, LDB);
            wmma::mma_sync(acc[n], a_hi, b_hi, acc[n]);
            wmma::mma_sync(acc[n], a_hi, b_lo, acc[n]);
            wmma::mma_sync(acc[n], a_lo, b_hi, acc[n]);
        }
    }
    float* po = reinterpret_cast<float*>(g_po);
#pragma unroll
    for (int n = 0; n < 5; n++)
        wmma::store_matrix_sync(po + (size_t)m0 * 80 + n * 16, acc[n], 80, wmma::mem_row_major);
}

// ------- out[n] = oz + b2 + mean(p_neigh) -------
__global__ __launch_bounds__(256) void k_agg2(float4* __restrict__ out) {
    int gw = (blockIdx.x * blockDim.x + threadIdx.x) >> 5;
    int lane = threadIdx.x & 31;
    int sub = lane / 10;
    int q = lane - sub * 10;
    int n = gw * 3 + sub;
    if (sub >= 3 || n >= N_NODES) return;
    const int* row = g_adj + (size_t)n * ELL_W;
    int cnt = g_cnt[n];
    if (cnt > ELL_W) cnt = ELL_W;
    float4 acc = make_float4(0.f, 0.f, 0.f, 0.f);
    int i = 0;
    for (; i + 8 <= cnt; i += 8) {
        int4 s4 = *reinterpret_cast<const int4*>(row + i);
        int4 s8 = *reinterpret_cast<const int4*>(row + i + 4);
        float4 v0 = g_po[(size_t)s4.x * 20 + q];
        float4 v1 = g_po[(size_t)s4.y * 20 + q];
        float4 v2 = g_po[(size_t)s4.z * 20 + q];
        float4 v3 = g_po[(size_t)s4.w * 20 + q];
        float4 v4 = g_po[(size_t)s8.x * 20 + q];
        float4 v5 = g_po[(size_t)s8.y * 20 + q];
        float4 v6 = g_po[(size_t)s8.z * 20 + q];
        float4 v7 = g_po[(size_t)s8.w * 20 + q];
        acc.x += ((v0.x + v1.x) + (v2.x + v3.x)) + ((v4.x + v5.x) + (v6.x + v7.x));
        acc.y += ((v0.y + v1.y) + (v2.y + v3.y)) + ((v4.y + v5.y) + (v6.y + v7.y));
        acc.z += ((v0.z + v1.z) + (v2.z + v3.z)) + ((v4.z + v5.z) + (v6.z + v7.z));
        acc.w += ((v0.w + v1.w) + (v2.w + v3.w)) + ((v4.w + v5.w) + (v6.w + v7.w));
    }
    for (; i + 4 <= cnt; i += 4) {
        int4 s4 = *reinterpret_cast<const int4*>(row + i);
        float4 v0 = g_po[(size_t)s4.x * 20 + q];
        float4 v1 = g_po[(size_t)s4.y * 20 + q];
        float4 v2 = g_po[(size_t)s4.z * 20 + q];
        float4 v3 = g_po[(size_t)s4.w * 20 + q];
        acc.x += (v0.x + v1.x) + (v2.x + v3.x);
        acc.y += (v0.y + v1.y) + (v2.y + v3.y);
        acc.z += (v0.z + v1.z) + (v2.z + v3.z);
        acc.w += (v0.w + v1.w) + (v2.w + v3.w);
    }
    for (; i < cnt; i++) {
        int s = row[i];
        float4 v = g_po[(size_t)s * 20 + q];
        acc.x += v.x; acc.y += v.y; acc.z += v.z; acc.w += v.w;
    }
    float inv = 1.0f / (float)(cnt > 0 ? cnt : 1);
    float4 oz = g_po[(size_t)n * 20 + 10 + q];
    float4 b = reinterpret_cast<const float4*>(c_b2)[q];
    float4 o;
    o.x = fmaf(acc.x, inv, oz.x + b.x);
    o.y = fmaf(acc.y, inv, oz.y + b.y);
    o.z = fmaf(acc.z, inv, oz.z + b.z);
    o.w = fmaf(acc.w, inv, oz.w + b.w);
    out[(size_t)n * 10 + q] = o;
}

// ---------------- launch ----------------
extern "C" void kernel_launch(void* const* d_in, const int* in_sizes, int n_in,
                              void* d_out, int out_size) {
    const float* x     = (const float*)d_in[0];
    const int*   ei    = (const int*)d_in[1];
    const float* gamma = (const float*)d_in[5];
    const float* beta  = (const float*)d_in[6];
    const int* src = ei;
    const int* dst = ei + E_EDGES;

    static cudaStream_t s2 = nullptr;
    static cudaEvent_t ev_fork = nullptr, ev_join = nullptr;
    if (s2 == nullptr) {   // created once on the uncaptured correctness call
        cudaStreamCreateWithFlags(&s2, cudaStreamNonBlocking);
        cudaEventCreateWithFlags(&ev_fork, cudaEventDisableTiming);
        cudaEventCreateWithFlags(&ev_join, cudaEventDisableTiming);
    }

    cudaMemcpyToSymbolAsync(g_W1, d_in[2], D_HID * D_IN * sizeof(float), 0,     cudaMemcpyDeviceToDevice, 0);
    cudaMemcpyToSymbolAsync(g_W1, d_in[3], D_HID * D_IN * sizeof(float), 16384, cudaMemcpyDeviceToDevice, 0);
    cudaMemcpyToSymbolAsync(c_b1, d_in[4], D_HID * sizeof(float), 0,            cudaMemcpyDeviceToDevice, 0);
    cudaMemcpyToSymbolAsync(g_W2, d_in[7], D_OUT * D_HID * sizeof(float), 0,     cudaMemcpyDeviceToDevice, 0);
    cudaMemcpyToSymbolAsync(g_W2, d_in[8], D_OUT * D_HID * sizeof(float), 10240, cudaMemcpyDeviceToDevice, 0);
    cudaMemcpyToSymbolAsync(c_b2, d_in[9], D_OUT * sizeof(float), 0,             cudaMemcpyDeviceToDevice, 0);

    const int p1_smem = 2 * 128 * LDB * (int)sizeof(float);                  // 69632 B
    const int p2_smem = (128 * LDB + 2 * 80 * LDB) * (int)sizeof(float);     // 78336 B
    cudaFuncSetAttribute(k_proj1_w, cudaFuncAttributeMaxDynamicSharedMemorySize, p1_smem);
    cudaFuncSetAttribute(k_bnproj2, cudaFuncAttributeMaxDynamicSharedMemorySize, p2_smem);

    k_zero<<<256, 256>>>();

    // fork: countfill (atomic-bound) overlaps proj1 (tensor-bound)
    cudaEventRecord(ev_fork, 0);
    cudaStreamWaitEvent(s2, ev_fork, 0);
    k_countfill<<<(E_EDGES / 8 + 255) / 256, 256, 0, s2>>>(src, dst);
    cudaEventRecord(ev_join, s2);

    k_proj1_w<<<(N_NODES + 127) / 128, 256, p1_smem>>>(x);

    // join: agg1h needs both adj (s2) and y/t (stream 0)
    cudaStreamWaitEvent(0, ev_join, 0);
    k_agg1h<<<(N_NODES + 63) / 64, 256>>>();

    // BN finalize + ReLU + layer-2 projection (fused)
    k_bnproj2<<<(N_NODES + 127) / 128, 256, p2_smem>>>(gamma, beta);

    // Layer 2 gather: out = oz + b2 + mean(p)
    k_agg2<<<(N_NODES / 3 + 8) / 8, 256>>>((float4*)d_out);
}